// round 2
// baseline (speedup 1.0000x reference)
#include <cuda_runtime.h>
#include <math.h>

#define B_ 8
#define N_ 2048
#define D_ 128
#define ND ((size_t)N_ * D_)
#define NNE ((size_t)N_ * N_)

// ---------------- scratch (device globals: allocation-free rule) ----------------
__device__ float g_H1[B_ * N_ * D_];
__device__ float g_H2[B_ * N_ * D_];
__device__ float g_V1[B_ * N_ * D_];
__device__ float g_V2[B_ * N_ * D_];
__device__ float g_E[(size_t)B_ * N_ * N_];   // 134 MB fp32 logits
__device__ float g_rmax[B_ * N_];
__device__ float g_rinv[B_ * N_];
__device__ float g_cmax[B_ * N_];
__device__ float g_cinv[B_ * N_];
__device__ float g_n12[B_ * N_ * D_];
__device__ float g_n21[B_ * N_ * D_];

// ---------------- shared 128x128 NT tile core (inner K = 128) ----------------
// C_tile[128x128] = A[128x128] * B[128x128]^T, both row-major ld=128.
// 256 threads, 8x8 microtile per thread.
__device__ __forceinline__ void nt_core(const float* __restrict__ A,
                                        const float* __restrict__ Bm,
                                        float acc[8][8],
                                        float (*sA)[132], float (*sB)[132],
                                        int t, int tm, int tn)
{
#pragma unroll 1
    for (int kc = 0; kc < 128; kc += 32) {
#pragma unroll
        for (int i = 0; i < 4; i++) {
            int idx = t + i * 256;
            int r = idx >> 3, cg = idx & 7;
            float4 v = *reinterpret_cast<const float4*>(A + (size_t)r * 128 + kc + cg * 4);
            sA[cg * 4 + 0][r] = v.x; sA[cg * 4 + 1][r] = v.y;
            sA[cg * 4 + 2][r] = v.z; sA[cg * 4 + 3][r] = v.w;
            float4 w = *reinterpret_cast<const float4*>(Bm + (size_t)r * 128 + kc + cg * 4);
            sB[cg * 4 + 0][r] = w.x; sB[cg * 4 + 1][r] = w.y;
            sB[cg * 4 + 2][r] = w.z; sB[cg * 4 + 3][r] = w.w;
        }
        __syncthreads();
#pragma unroll 8
        for (int k = 0; k < 32; k++) {
            float a[8], b[8];
            *(float4*)&a[0] = *(const float4*)&sA[k][tm];
            *(float4*)&a[4] = *(const float4*)&sA[k][tm + 4];
            *(float4*)&b[0] = *(const float4*)&sB[k][tn];
            *(float4*)&b[4] = *(const float4*)&sB[k][tn + 4];
#pragma unroll
            for (int i = 0; i < 8; i++)
#pragma unroll
                for (int j = 0; j < 8; j++)
                    acc[i][j] = fmaf(a[i], b[j], acc[i][j]);
        }
        __syncthreads();
    }
}

// ---------------- projections: H1/H2/V1/V2 = X @ W^T ----------------
__global__ void __launch_bounds__(256) k_proj(const float* __restrict__ x1,
                                              const float* __restrict__ x2,
                                              const float* __restrict__ Wk,
                                              const float* __restrict__ Wv)
{
    __shared__ float sA[32][132], sB[32][132];
    int which = blockIdx.y;                       // 0:H1 1:H2 2:V1 3:V2
    const float* A = (which & 1) ? x2 : x1;
    const float* W = (which < 2) ? Wk : Wv;
    float* C = which == 0 ? g_H1 : which == 1 ? g_H2 : which == 2 ? g_V1 : g_V2;
    size_t row0 = (size_t)blockIdx.x * 128;
    int t = threadIdx.x, tm = (t >> 4) << 3, tn = (t & 15) << 3;
    float acc[8][8] = {};
    nt_core(A + row0 * 128, W, acc, sA, sB, t, tm, tn);
#pragma unroll
    for (int i = 0; i < 8; i++) {
        *(float4*)&C[(row0 + tm + i) * 128 + tn]     = make_float4(acc[i][0], acc[i][1], acc[i][2], acc[i][3]);
        *(float4*)&C[(row0 + tm + i) * 128 + tn + 4] = make_float4(acc[i][4], acc[i][5], acc[i][6], acc[i][7]);
    }
}

// ---------------- E = H1 @ H2^T per batch ----------------
__global__ void __launch_bounds__(256) k_e()
{
    __shared__ float sA[32][132], sB[32][132];
    int b = blockIdx.z;
    size_t n0 = (size_t)blockIdx.y * 128, m0 = (size_t)blockIdx.x * 128;
    const float* A  = g_H1 + ((size_t)b * N_ + n0) * D_;
    const float* Bm = g_H2 + ((size_t)b * N_ + m0) * D_;
    int t = threadIdx.x, tm = (t >> 4) << 3, tn = (t & 15) << 3;
    float acc[8][8] = {};
    nt_core(A, Bm, acc, sA, sB, t, tm, tn);
    float* C = g_E + (size_t)b * NNE;
#pragma unroll
    for (int i = 0; i < 8; i++) {
        *(float4*)&C[(n0 + tm + i) * N_ + m0 + tn]     = make_float4(acc[i][0], acc[i][1], acc[i][2], acc[i][3]);
        *(float4*)&C[(n0 + tm + i) * N_ + m0 + tn + 4] = make_float4(acc[i][4], acc[i][5], acc[i][6], acc[i][7]);
    }
}

// ---------------- online (max, sum-exp) merge ----------------
__device__ __forceinline__ void lse_merge(float& m, float& s, float m2, float s2)
{
    float M = fmaxf(m, m2);
    s = s * __expf(m - M) + s2 * __expf(m2 - M);
    m = M;
}

// row stats: over m (last axis) for each row n  -> used by a21 path
__global__ void k_rowstats()
{
    int row = blockIdx.x;                          // b*N_ + n
    const float* e = g_E + (size_t)row * N_;
    int t = threadIdx.x;
    float m = -3e38f, s = 0.f;
#pragma unroll
    for (int j = 0; j < 8; j++) {
        float x = e[t + j * 256];
        if (x > m) { s = s * __expf(m - x) + 1.f; m = x; }
        else       { s += __expf(x - m); }
    }
    __shared__ float sm[256], ss[256];
    sm[t] = m; ss[t] = s;
    __syncthreads();
    for (int off = 128; off > 0; off >>= 1) {
        if (t < off) {
            float mm = sm[t], sv = ss[t];
            lse_merge(mm, sv, sm[t + off], ss[t + off]);
            sm[t] = mm; ss[t] = sv;
        }
        __syncthreads();
    }
    if (t == 0) { g_rmax[row] = sm[0]; g_rinv[row] = 1.f / ss[0]; }
}

// col stats: over n (first axis) for each column m -> used by a12 path
__global__ void k_colstats()
{
    int b = blockIdx.y;
    int m = blockIdx.x * 256 + threadIdx.x;
    const float* e = g_E + (size_t)b * NNE + m;
    float mx[4] = {-3e38f, -3e38f, -3e38f, -3e38f};
    float s[4]  = {0.f, 0.f, 0.f, 0.f};
#pragma unroll 1
    for (int n = 0; n < N_; n += 4) {
#pragma unroll
        for (int u = 0; u < 4; u++) {
            float x = e[(size_t)(n + u) * N_];
            if (x > mx[u]) { s[u] = s[u] * __expf(mx[u] - x) + 1.f; mx[u] = x; }
            else           { s[u] += __expf(x - mx[u]); }
        }
    }
    lse_merge(mx[0], s[0], mx[1], s[1]);
    lse_merge(mx[2], s[2], mx[3], s[3]);
    lse_merge(mx[0], s[0], mx[2], s[2]);
    g_cmax[b * N_ + m] = mx[0];
    g_cinv[b * N_ + m] = 1.f / s[0];
}

// ---------------- n12[n,k] = sum_m exp(E[n,m]-c_m) * V2[m,k]/s_m ----------------
__global__ void __launch_bounds__(256) k_n12()
{
    __shared__ float sA[32][132];   // [m_local][n]
    __shared__ float sB[32][132];   // [m_local][k]
    int b = blockIdx.y;
    size_t n0 = (size_t)blockIdx.x * 128;
    const float* E    = g_E + (size_t)b * NNE;
    const float* V    = g_V2 + (size_t)b * ND;
    const float* cmax = g_cmax + b * N_;
    const float* cinv = g_cinv + b * N_;
    int t = threadIdx.x, tm = (t >> 4) << 3, tn = (t & 15) << 3;
    float acc[8][8] = {};
#pragma unroll 1
    for (int mc = 0; mc < N_; mc += 32) {
#pragma unroll
        for (int i = 0; i < 4; i++) {                // E tile 128n x 32m, exp-shift, transpose
            int idx = t + i * 256;
            int r = idx >> 3, cg = idx & 7;
            float4 v  = *(const float4*)&E[(n0 + r) * (size_t)N_ + mc + cg * 4];
            float4 cm = *(const float4*)&cmax[mc + cg * 4];
            sA[cg * 4 + 0][r] = __expf(v.x - cm.x);
            sA[cg * 4 + 1][r] = __expf(v.y - cm.y);
            sA[cg * 4 + 2][r] = __expf(v.z - cm.z);
            sA[cg * 4 + 3][r] = __expf(v.w - cm.w);
        }
#pragma unroll
        for (int i = 0; i < 4; i++) {                // V2 tile 32m x 128k, scaled by 1/s_m
            int idx = t + i * 256;
            int r = idx >> 5, cg = idx & 31;
            float4 v = *(const float4*)&V[(size_t)(mc + r) * D_ + cg * 4];
            float sc = cinv[mc + r];
            *(float4*)&sB[r][cg * 4] = make_float4(v.x * sc, v.y * sc, v.z * sc, v.w * sc);
        }
        __syncthreads();
#pragma unroll 8
        for (int k = 0; k < 32; k++) {
            float a[8], bb[8];
            *(float4*)&a[0]  = *(const float4*)&sA[k][tm];
            *(float4*)&a[4]  = *(const float4*)&sA[k][tm + 4];
            *(float4*)&bb[0] = *(const float4*)&sB[k][tn];
            *(float4*)&bb[4] = *(const float4*)&sB[k][tn + 4];
#pragma unroll
            for (int i = 0; i < 8; i++)
#pragma unroll
                for (int j = 0; j < 8; j++)
                    acc[i][j] = fmaf(a[i], bb[j], acc[i][j]);
        }
        __syncthreads();
    }
    float* C = g_n12 + (size_t)b * ND;
#pragma unroll
    for (int i = 0; i < 8; i++) {
        *(float4*)&C[(n0 + tm + i) * D_ + tn]     = make_float4(acc[i][0], acc[i][1], acc[i][2], acc[i][3]);
        *(float4*)&C[(n0 + tm + i) * D_ + tn + 4] = make_float4(acc[i][4], acc[i][5], acc[i][6], acc[i][7]);
    }
}

// ---------------- n21[m,k] = sum_n exp(E[n,m]-r_n) * V1[n,k]/t_n ----------------
__global__ void __launch_bounds__(256) k_n21()
{
    __shared__ float sA[32][132];   // [n_local][m]
    __shared__ float sB[32][132];   // [n_local][k]
    int b = blockIdx.y;
    size_t m0 = (size_t)blockIdx.x * 128;
    const float* E    = g_E + (size_t)b * NNE;
    const float* V    = g_V1 + (size_t)b * ND;
    const float* rmax = g_rmax + b * N_;
    const float* rinv = g_rinv + b * N_;
    int t = threadIdx.x, tm = (t >> 4) << 3, tn = (t & 15) << 3;
    float acc[8][8] = {};
#pragma unroll 1
    for (int nc = 0; nc < N_; nc += 32) {
#pragma unroll
        for (int i = 0; i < 4; i++) {                // E tile 32n x 128m, exp-shift (per-row)
            int idx = t + i * 256;
            int r = idx >> 5, cg = idx & 31;
            float4 v = *(const float4*)&E[(size_t)(nc + r) * N_ + m0 + cg * 4];
            float rm = rmax[nc + r];
            *(float4*)&sA[r][cg * 4] = make_float4(__expf(v.x - rm), __expf(v.y - rm),
                                                   __expf(v.z - rm), __expf(v.w - rm));
        }
#pragma unroll
        for (int i = 0; i < 4; i++) {                // V1 tile 32n x 128k, scaled by 1/t_n
            int idx = t + i * 256;
            int r = idx >> 5, cg = idx & 31;
            float4 v = *(const float4*)&V[(size_t)(nc + r) * D_ + cg * 4];
            float sc = rinv[nc + r];
            *(float4*)&sB[r][cg * 4] = make_float4(v.x * sc, v.y * sc, v.z * sc, v.w * sc);
        }
        __syncthreads();
#pragma unroll 8
        for (int k = 0; k < 32; k++) {
            float a[8], bb[8];
            *(float4*)&a[0]  = *(const float4*)&sA[k][tm];
            *(float4*)&a[4]  = *(const float4*)&sA[k][tm + 4];
            *(float4*)&bb[0] = *(const float4*)&sB[k][tn];
            *(float4*)&bb[4] = *(const float4*)&sB[k][tn + 4];
#pragma unroll
            for (int i = 0; i < 8; i++)
#pragma unroll
                for (int j = 0; j < 8; j++)
                    acc[i][j] = fmaf(a[i], bb[j], acc[i][j]);
        }
        __syncthreads();
    }
    float* C = g_n21 + (size_t)b * ND;
#pragma unroll
    for (int i = 0; i < 8; i++) {
        *(float4*)&C[(m0 + tm + i) * D_ + tn]     = make_float4(acc[i][0], acc[i][1], acc[i][2], acc[i][3]);
        *(float4*)&C[(m0 + tm + i) * D_ + tn + 4] = make_float4(acc[i][4], acc[i][5], acc[i][6], acc[i][7]);
    }
}

// ---------------- msg = leaky_relu(n @ Wo^T + bo) ----------------
__global__ void __launch_bounds__(256) k_msg(const float* __restrict__ Wo,
                                             const float* __restrict__ bo,
                                             float* __restrict__ out)
{
    __shared__ float sA[32][132], sB[32][132];
    int which = blockIdx.y;                          // 0: msg1 (n12)  1: msg2 (n21)
    const float* A = which ? g_n21 : g_n12;
    float* C = out + (size_t)which * (B_ * ND);
    size_t row0 = (size_t)blockIdx.x * 128;
    int t = threadIdx.x, tm = (t >> 4) << 3, tn = (t & 15) << 3;
    float acc[8][8] = {};
    nt_core(A + row0 * 128, Wo, acc, sA, sB, t, tm, tn);
#pragma unroll
    for (int i = 0; i < 8; i++) {
        float v[8];
#pragma unroll
        for (int j = 0; j < 8; j++) {
            float x = acc[i][j] + bo[tn + j];
            v[j] = x > 0.f ? x : 0.01f * x;
        }
        *(float4*)&C[(row0 + tm + i) * 128 + tn]     = make_float4(v[0], v[1], v[2], v[3]);
        *(float4*)&C[(row0 + tm + i) * 128 + tn + 4] = make_float4(v[4], v[5], v[6], v[7]);
    }
}

// ---------------- launch ----------------
extern "C" void kernel_launch(void* const* d_in, const int* in_sizes, int n_in,
                              void* d_out, int out_size)
{
    const float* x1 = (const float*)d_in[0];
    const float* x2 = (const float*)d_in[1];
    const float* Wk = (const float*)d_in[2];
    const float* Wv = (const float*)d_in[3];
    const float* Wo = (const float*)d_in[4];
    const float* bo = (const float*)d_in[5];
    float* out = (float*)d_out;

    k_proj<<<dim3(128, 4), 256>>>(x1, x2, Wk, Wv);           // H1,H2,V1,V2
    k_e<<<dim3(16, 16, 8), 256>>>();                         // E = H1 @ H2^T
    k_rowstats<<<B_ * N_, 256>>>();                          // r_n, 1/t_n
    k_colstats<<<dim3(8, B_), 256>>>();                      // c_m, 1/s_m
    k_n12<<<dim3(16, B_), 256>>>();                          // exp-weighted GEMM 1
    k_n21<<<dim3(16, B_), 256>>>();                          // exp-weighted GEMM 2
    k_msg<<<dim3(128, 2), 256>>>(Wo, bo, out);               // output proj + bias + leaky
}

// round 4
// speedup vs baseline: 1.4573x; 1.4573x over previous
#include <cuda_runtime.h>
#include <math.h>

#define B_ 8
#define N_ 2048
#define D_ 128
#define NSPLIT 16
#define ND ((size_t)N_ * D_)
#define NNE ((size_t)N_ * N_)

// ---------------- scratch (device globals: allocation-free rule) ----------------
__device__ float g_H1[B_ * N_ * D_];
__device__ float g_H2[B_ * N_ * D_];
__device__ float g_V1[B_ * N_ * D_];
__device__ float g_V2[B_ * N_ * D_];
__device__ float g_E[(size_t)B_ * N_ * N_];   // 134 MB fp32 logits
__device__ float g_rmax[B_ * N_];
__device__ float g_rinv[B_ * N_];
__device__ float g_cmax[B_ * N_];
__device__ float g_cinv[B_ * N_];
__device__ float g_pcmax[NSPLIT * B_ * N_];   // partial column stats
__device__ float g_pcsum[NSPLIT * B_ * N_];
__device__ float g_n12[B_ * N_ * D_];
__device__ float g_n21[B_ * N_ * D_];

// ---------------- shared 128x128 NT tile core (inner K = 128) ----------------
__device__ __forceinline__ void nt_core(const float* __restrict__ A,
                                        const float* __restrict__ Bm,
                                        float acc[8][8],
                                        float (*sA)[132], float (*sB)[132],
                                        int t, int tm, int tn)
{
#pragma unroll 1
    for (int kc = 0; kc < 128; kc += 32) {
#pragma unroll
        for (int i = 0; i < 4; i++) {
            int idx = t + i * 256;
            int r = idx >> 3, cg = idx & 7;
            float4 v = *reinterpret_cast<const float4*>(A + (size_t)r * 128 + kc + cg * 4);
            sA[cg * 4 + 0][r] = v.x; sA[cg * 4 + 1][r] = v.y;
            sA[cg * 4 + 2][r] = v.z; sA[cg * 4 + 3][r] = v.w;
            float4 w = *reinterpret_cast<const float4*>(Bm + (size_t)r * 128 + kc + cg * 4);
            sB[cg * 4 + 0][r] = w.x; sB[cg * 4 + 1][r] = w.y;
            sB[cg * 4 + 2][r] = w.z; sB[cg * 4 + 3][r] = w.w;
        }
        __syncthreads();
#pragma unroll 8
        for (int k = 0; k < 32; k++) {
            float a[8], b[8];
            *(float4*)&a[0] = *(const float4*)&sA[k][tm];
            *(float4*)&a[4] = *(const float4*)&sA[k][tm + 4];
            *(float4*)&b[0] = *(const float4*)&sB[k][tn];
            *(float4*)&b[4] = *(const float4*)&sB[k][tn + 4];
#pragma unroll
            for (int i = 0; i < 8; i++)
#pragma unroll
                for (int j = 0; j < 8; j++)
                    acc[i][j] = fmaf(a[i], b[j], acc[i][j]);
        }
        __syncthreads();
    }
}

// ---------------- projections: H1/H2/V1/V2 = X @ W^T ----------------
__global__ void __launch_bounds__(256) k_proj(const float* __restrict__ x1,
                                              const float* __restrict__ x2,
                                              const float* __restrict__ Wk,
                                              const float* __restrict__ Wv)
{
    __shared__ float sA[32][132], sB[32][132];
    int which = blockIdx.y;                       // 0:H1 1:H2 2:V1 3:V2
    const float* A = (which & 1) ? x2 : x1;
    const float* W = (which < 2) ? Wk : Wv;
    float* C = which == 0 ? g_H1 : which == 1 ? g_H2 : which == 2 ? g_V1 : g_V2;
    size_t row0 = (size_t)blockIdx.x * 128;
    int t = threadIdx.x, tm = (t >> 4) << 3, tn = (t & 15) << 3;
    float acc[8][8] = {};
    nt_core(A + row0 * 128, W, acc, sA, sB, t, tm, tn);
#pragma unroll
    for (int i = 0; i < 8; i++) {
        *(float4*)&C[(row0 + tm + i) * 128 + tn]     = make_float4(acc[i][0], acc[i][1], acc[i][2], acc[i][3]);
        *(float4*)&C[(row0 + tm + i) * 128 + tn + 4] = make_float4(acc[i][4], acc[i][5], acc[i][6], acc[i][7]);
    }
}

// ---------------- E = H1 @ H2^T per batch ----------------
__global__ void __launch_bounds__(256) k_e()
{
    __shared__ float sA[32][132], sB[32][132];
    int b = blockIdx.z;
    size_t n0 = (size_t)blockIdx.y * 128, m0 = (size_t)blockIdx.x * 128;
    const float* A  = g_H1 + ((size_t)b * N_ + n0) * D_;
    const float* Bm = g_H2 + ((size_t)b * N_ + m0) * D_;
    int t = threadIdx.x, tm = (t >> 4) << 3, tn = (t & 15) << 3;
    float acc[8][8] = {};
    nt_core(A, Bm, acc, sA, sB, t, tm, tn);
    float* C = g_E + (size_t)b * NNE;
#pragma unroll
    for (int i = 0; i < 8; i++) {
        *(float4*)&C[(n0 + tm + i) * N_ + m0 + tn]     = make_float4(acc[i][0], acc[i][1], acc[i][2], acc[i][3]);
        *(float4*)&C[(n0 + tm + i) * N_ + m0 + tn + 4] = make_float4(acc[i][4], acc[i][5], acc[i][6], acc[i][7]);
    }
}

// ---------------- online (max, sum-exp) merge ----------------
__device__ __forceinline__ void lse_merge(float& m, float& s, float m2, float s2)
{
    float M = fmaxf(m, m2);
    s = s * __expf(m - M) + s2 * __expf(m2 - M);
    m = M;
}

// row stats: over m (last axis) for each row n  -> used by a21 path
__global__ void k_rowstats()
{
    int row = blockIdx.x;                          // b*N_ + n
    const float* e = g_E + (size_t)row * N_;
    int t = threadIdx.x;
    float m = -3e38f, s = 0.f;
#pragma unroll
    for (int j = 0; j < 8; j++) {
        float x = e[t + j * 256];
        if (x > m) { s = s * __expf(m - x) + 1.f; m = x; }
        else       { s += __expf(x - m); }
    }
    __shared__ float sm[256], ss[256];
    sm[t] = m; ss[t] = s;
    __syncthreads();
    for (int off = 128; off > 0; off >>= 1) {
        if (t < off) {
            float mm = sm[t], sv = ss[t];
            lse_merge(mm, sv, sm[t + off], ss[t + off]);
            sm[t] = mm; ss[t] = sv;
        }
        __syncthreads();
    }
    if (t == 0) { g_rmax[row] = sm[0]; g_rinv[row] = 1.f / ss[0]; }
}

// col stats phase 1: each block reduces a 128-row slab for 256 columns
__global__ void k_colstats_p1()
{
    int b  = blockIdx.z;
    int ns = blockIdx.y;                            // n-split index
    int m  = blockIdx.x * 256 + threadIdx.x;
    const float* e = g_E + (size_t)b * NNE + (size_t)ns * 128 * N_ + m;
    float mx[4] = {-3e38f, -3e38f, -3e38f, -3e38f};
    float s[4]  = {0.f, 0.f, 0.f, 0.f};
#pragma unroll 1
    for (int n = 0; n < 128; n += 4) {
#pragma unroll
        for (int u = 0; u < 4; u++) {
            float x = e[(size_t)(n + u) * N_];
            if (x > mx[u]) { s[u] = s[u] * __expf(mx[u] - x) + 1.f; mx[u] = x; }
            else           { s[u] += __expf(x - mx[u]); }
        }
    }
    lse_merge(mx[0], s[0], mx[1], s[1]);
    lse_merge(mx[2], s[2], mx[3], s[3]);
    lse_merge(mx[0], s[0], mx[2], s[2]);
    g_pcmax[(ns * B_ + b) * N_ + m] = mx[0];
    g_pcsum[(ns * B_ + b) * N_ + m] = s[0];
}

// col stats phase 2: merge the NSPLIT partials per column
__global__ void k_colstats_p2()
{
    int b = blockIdx.y;
    int m = blockIdx.x * 256 + threadIdx.x;
    float mx = -3e38f, s = 0.f;
#pragma unroll
    for (int ns = 0; ns < NSPLIT; ns++) {
        float m2 = g_pcmax[(ns * B_ + b) * N_ + m];
        float s2 = g_pcsum[(ns * B_ + b) * N_ + m];
        lse_merge(mx, s, m2, s2);
    }
    g_cmax[b * N_ + m] = mx;
    g_cinv[b * N_ + m] = 1.f / s;
}

// ---------------- n12[n,k] = sum_m exp(E[n,m]-c_m) * V2[m,k]/s_m ----------------
__global__ void __launch_bounds__(256) k_n12()
{
    __shared__ float sA[32][132];   // [m_local][n]
    __shared__ float sB[32][132];   // [m_local][k]
    int b = blockIdx.y;
    size_t n0 = (size_t)blockIdx.x * 128;
    const float* E    = g_E + (size_t)b * NNE;
    const float* V    = g_V2 + (size_t)b * ND;
    const float* cmax = g_cmax + b * N_;
    const float* cinv = g_cinv + b * N_;
    int t = threadIdx.x, tm = (t >> 4) << 3, tn = (t & 15) << 3;
    float acc[8][8] = {};
#pragma unroll 1
    for (int mc = 0; mc < N_; mc += 32) {
#pragma unroll
        for (int i = 0; i < 4; i++) {                // E tile 128n x 32m, exp-shift, transpose
            int idx = t + i * 256;
            int r = idx >> 3, cg = idx & 7;
            float4 v  = *(const float4*)&E[(n0 + r) * (size_t)N_ + mc + cg * 4];
            float4 cm = *(const float4*)&cmax[mc + cg * 4];
            sA[cg * 4 + 0][r] = __expf(v.x - cm.x);
            sA[cg * 4 + 1][r] = __expf(v.y - cm.y);
            sA[cg * 4 + 2][r] = __expf(v.z - cm.z);
            sA[cg * 4 + 3][r] = __expf(v.w - cm.w);
        }
#pragma unroll
        for (int i = 0; i < 4; i++) {                // V2 tile 32m x 128k, scaled by 1/s_m
            int idx = t + i * 256;
            int r = idx >> 5, cg = idx & 31;
            float4 v = *(const float4*)&V[(size_t)(mc + r) * D_ + cg * 4];
            float sc = cinv[mc + r];
            *(float4*)&sB[r][cg * 4] = make_float4(v.x * sc, v.y * sc, v.z * sc, v.w * sc);
        }
        __syncthreads();
#pragma unroll 8
        for (int k = 0; k < 32; k++) {
            float a[8], bb[8];
            *(float4*)&a[0]  = *(const float4*)&sA[k][tm];
            *(float4*)&a[4]  = *(const float4*)&sA[k][tm + 4];
            *(float4*)&bb[0] = *(const float4*)&sB[k][tn];
            *(float4*)&bb[4] = *(const float4*)&sB[k][tn + 4];
#pragma unroll
            for (int i = 0; i < 8; i++)
#pragma unroll
                for (int j = 0; j < 8; j++)
                    acc[i][j] = fmaf(a[i], bb[j], acc[i][j]);
        }
        __syncthreads();
    }
    float* C = g_n12 + (size_t)b * ND;
#pragma unroll
    for (int i = 0; i < 8; i++) {
        *(float4*)&C[(n0 + tm + i) * D_ + tn]     = make_float4(acc[i][0], acc[i][1], acc[i][2], acc[i][3]);
        *(float4*)&C[(n0 + tm + i) * D_ + tn + 4] = make_float4(acc[i][4], acc[i][5], acc[i][6], acc[i][7]);
    }
}

// ---------------- n21[m,k] = sum_n exp(E[n,m]-r_n) * V1[n,k]/t_n ----------------
__global__ void __launch_bounds__(256) k_n21()
{
    __shared__ float sA[32][132];   // [n_local][m]
    __shared__ float sB[32][132];   // [n_local][k]
    int b = blockIdx.y;
    size_t m0 = (size_t)blockIdx.x * 128;
    const float* E    = g_E + (size_t)b * NNE;
    const float* V    = g_V1 + (size_t)b * ND;
    const float* rmax = g_rmax + b * N_;
    const float* rinv = g_rinv + b * N_;
    int t = threadIdx.x, tm = (t >> 4) << 3, tn = (t & 15) << 3;
    float acc[8][8] = {};
#pragma unroll 1
    for (int nc = 0; nc < N_; nc += 32) {
#pragma unroll
        for (int i = 0; i < 4; i++) {                // E tile 32n x 128m, exp-shift (per-row)
            int idx = t + i * 256;
            int r = idx >> 5, cg = idx & 31;
            float4 v = *(const float4*)&E[(size_t)(nc + r) * N_ + m0 + cg * 4];
            float rm = rmax[nc + r];
            *(float4*)&sA[r][cg * 4] = make_float4(__expf(v.x - rm), __expf(v.y - rm),
                                                   __expf(v.z - rm), __expf(v.w - rm));
        }
#pragma unroll
        for (int i = 0; i < 4; i++) {                // V1 tile 32n x 128k, scaled by 1/t_n
            int idx = t + i * 256;
            int r = idx >> 5, cg = idx & 31;
            float4 v = *(const float4*)&V[(size_t)(nc + r) * D_ + cg * 4];
            float sc = rinv[nc + r];
            *(float4*)&sB[r][cg * 4] = make_float4(v.x * sc, v.y * sc, v.z * sc, v.w * sc);
        }
        __syncthreads();
#pragma unroll 8
        for (int k = 0; k < 32; k++) {
            float a[8], bb[8];
            *(float4*)&a[0]  = *(const float4*)&sA[k][tm];
            *(float4*)&a[4]  = *(const float4*)&sA[k][tm + 4];
            *(float4*)&bb[0] = *(const float4*)&sB[k][tn];
            *(float4*)&bb[4] = *(const float4*)&sB[k][tn + 4];
#pragma unroll
            for (int i = 0; i < 8; i++)
#pragma unroll
                for (int j = 0; j < 8; j++)
                    acc[i][j] = fmaf(a[i], bb[j], acc[i][j]);
        }
        __syncthreads();
    }
    float* C = g_n21 + (size_t)b * ND;
#pragma unroll
    for (int i = 0; i < 8; i++) {
        *(float4*)&C[(m0 + tm + i) * D_ + tn]     = make_float4(acc[i][0], acc[i][1], acc[i][2], acc[i][3]);
        *(float4*)&C[(m0 + tm + i) * D_ + tn + 4] = make_float4(acc[i][4], acc[i][5], acc[i][6], acc[i][7]);
    }
}

// ---------------- msg = leaky_relu(n @ Wo^T + bo) ----------------
__global__ void __launch_bounds__(256) k_msg(const float* __restrict__ Wo,
                                             const float* __restrict__ bo,
                                             float* __restrict__ out)
{
    __shared__ float sA[32][132], sB[32][132];
    int which = blockIdx.y;                          // 0: msg1 (n12)  1: msg2 (n21)
    const float* A = which ? g_n21 : g_n12;
    float* C = out + (size_t)which * (B_ * ND);
    size_t row0 = (size_t)blockIdx.x * 128;
    int t = threadIdx.x, tm = (t >> 4) << 3, tn = (t & 15) << 3;
    float acc[8][8] = {};
    nt_core(A + row0 * 128, Wo, acc, sA, sB, t, tm, tn);
#pragma unroll
    for (int i = 0; i < 8; i++) {
        float v[8];
#pragma unroll
        for (int j = 0; j < 8; j++) {
            float x = acc[i][j] + bo[tn + j];
            v[j] = x > 0.f ? x : 0.01f * x;
        }
        *(float4*)&C[(row0 + tm + i) * 128 + tn]     = make_float4(v[0], v[1], v[2], v[3]);
        *(float4*)&C[(row0 + tm + i) * 128 + tn + 4] = make_float4(v[4], v[5], v[6], v[7]);
    }
}

// ---------------- launch ----------------
extern "C" void kernel_launch(void* const* d_in, const int* in_sizes, int n_in,
                              void* d_out, int out_size)
{
    const float* x1 = (const float*)d_in[0];
    const float* x2 = (const float*)d_in[1];
    const float* Wk = (const float*)d_in[2];
    const float* Wv = (const float*)d_in[3];
    const float* Wo = (const float*)d_in[4];
    const float* bo = (const float*)d_in[5];
    float* out = (float*)d_out;

    k_proj<<<dim3(128, 4), 256>>>(x1, x2, Wk, Wv);           // H1,H2,V1,V2
    k_e<<<dim3(16, 16, 8), 256>>>();                         // E = H1 @ H2^T
    k_rowstats<<<B_ * N_, 256>>>();                          // r_n, 1/t_n
    k_colstats_p1<<<dim3(8, NSPLIT, B_), 256>>>();           // partial col stats
    k_colstats_p2<<<dim3(8, B_), 256>>>();                   // merge -> c_m, 1/s_m
    k_n12<<<dim3(16, B_), 256>>>();                          // exp-weighted GEMM 1
    k_n21<<<dim3(16, B_), 256>>>();                          // exp-weighted GEMM 2
    k_msg<<<dim3(128, 2), 256>>>(Wo, bo, out);               // output proj + bias + leaky
}